// round 3
// baseline (speedup 1.0000x reference)
#include <cuda_runtime.h>
#include <cuda_bf16.h>
#include <cstdint>

// Problem constants (fixed shapes)
static constexpr int B_  = 64;
static constexpr int N_  = 2048;
static constexpr int D_  = 128;
static constexpr int K_  = 1024;           // ceil(0.5 * N)
static constexpr int BN_ = B_ * N_;        // 131072 nodes
static constexpr int BK_ = B_ * K_;        // 65536 kept nodes
static constexpr int E_  = BN_ * 32;       // 4194304 edges

// ---------------- scratch (device globals; no allocation allowed) ----------
__device__ int          g_outdeg[BN_];
__device__ int          g_indeg[BN_];
__device__ double       g_m[BN_];          // s * inv_sqrt_out   (double)
__device__ double       g_sum[BN_];        // segment sum        (double)
__device__ float        g_score[BN_];      // final fp32 score (correctly rounded)
__device__ float        g_t[BN_];          // tanh(score)
__device__ int          g_perm[BK_];
__device__ int          g_perm_com[BK_];
__device__ unsigned int g_smax_ord;        // ordered-uint encoded global max
__device__ float        g_sumexp;

// monotonic float<->uint mapping
__device__ __forceinline__ unsigned int ford(float f) {
    unsigned int u = __float_as_uint(f);
    return (u & 0x80000000u) ? ~u : (u | 0x80000000u);
}
__device__ __forceinline__ float fdeord(unsigned int u) {
    unsigned int v = (u & 0x80000000u) ? (u & 0x7FFFFFFFu) : ~u;
    return __uint_as_float(v);
}

// ---------------- kernels ---------------------------------------------------

__global__ void init_kernel() {
    int i = blockIdx.x * blockDim.x + threadIdx.x;
    if (i < BN_) {
        g_outdeg[i] = 0;
        g_indeg[i]  = 0;
        g_sum[i]    = 0.0;
    }
    if (i == 0) {
        g_smax_ord = 0u;      // encodes most-negative float
        g_sumexp   = 0.0f;
    }
}

__global__ void deg_kernel(const int* __restrict__ src, const int* __restrict__ dst) {
    int e = blockIdx.x * blockDim.x + threadIdx.x;
    if (e >= E_) return;
    atomicAdd(&g_outdeg[src[e]], 1);
    atomicAdd(&g_indeg[dst[e]], 1);
}

// s = feature @ W (double) ; m = s / sqrt(max(outdeg,1)) (double).
// One warp per node row.
__global__ void proj_kernel(const float* __restrict__ feat, const float* __restrict__ W) {
    int gtid = blockIdx.x * blockDim.x + threadIdx.x;
    int w    = gtid >> 5;
    int lane = gtid & 31;
    if (w >= BN_) return;
    const float4* fr = reinterpret_cast<const float4*>(feat + (size_t)w * D_);
    const float4* wr = reinterpret_cast<const float4*>(W);
    float4 f = __ldg(fr + lane);
    float4 wv = __ldg(wr + lane);
    double s = (double)f.x * (double)wv.x;
    s = fma((double)f.y, (double)wv.y, s);
    s = fma((double)f.z, (double)wv.z, s);
    s = fma((double)f.w, (double)wv.w, s);
    #pragma unroll
    for (int o = 16; o > 0; o >>= 1) s += __shfl_xor_sync(0xFFFFFFFFu, s, o);
    if (lane == 0) {
        double od = (double)max(g_outdeg[w], 1);
        g_m[w] = s / sqrt(od);
    }
}

__global__ void scatter_kernel(const int* __restrict__ src, const int* __restrict__ dst) {
    int e = blockIdx.x * blockDim.x + threadIdx.x;
    if (e >= E_) return;
    double v = g_m[src[e]];
    atomicAdd(&g_sum[dst[e]], v);
}

// score = (double)sum / sqrt(max(indeg,1)) + b -> round to fp32;
// t = tanh(score) ; global max of fp32 scores.
__global__ void finalize_kernel(const float* __restrict__ b) {
    int v = blockIdx.x * blockDim.x + threadIdx.x;
    float sc = -3.4e38f;
    if (v < BN_) {
        double id = (double)max(g_indeg[v], 1);
        double sd = g_sum[v] / sqrt(id) + (double)__ldg(b);
        sc = (float)sd;
        g_score[v] = sc;
        g_t[v] = tanhf(sc);
    }
    __shared__ float sm[32];
    float m = sc;
    #pragma unroll
    for (int o = 16; o > 0; o >>= 1) m = fmaxf(m, __shfl_xor_sync(0xFFFFFFFFu, m, o));
    int lane = threadIdx.x & 31, wid = threadIdx.x >> 5;
    if (lane == 0) sm[wid] = m;
    __syncthreads();
    if (wid == 0) {
        m = (lane < (blockDim.x >> 5)) ? sm[lane] : -3.4e38f;
        #pragma unroll
        for (int o = 16; o > 0; o >>= 1) m = fmaxf(m, __shfl_xor_sync(0xFFFFFFFFu, m, o));
        if (lane == 0) atomicMax(&g_smax_ord, ford(m));
    }
}

__global__ void sumexp_kernel() {
    int v = blockIdx.x * blockDim.x + threadIdx.x;
    float smax = fdeord(g_smax_ord);
    float e = 0.0f;
    if (v < BN_) e = __expf(g_score[v] - smax);
    __shared__ float sm[32];
    #pragma unroll
    for (int o = 16; o > 0; o >>= 1) e += __shfl_xor_sync(0xFFFFFFFFu, e, o);
    int lane = threadIdx.x & 31, wid = threadIdx.x >> 5;
    if (lane == 0) sm[wid] = e;
    __syncthreads();
    if (wid == 0) {
        e = (lane < (blockDim.x >> 5)) ? sm[lane] : 0.0f;
        #pragma unroll
        for (int o = 16; o > 0; o >>= 1) e += __shfl_xor_sync(0xFFFFFFFFu, e, o);
        if (lane == 0) atomicAdd(&g_sumexp, e);
    }
}

// Per-graph: bitonic sort 2048 composite keys -> perm (top-K desc score,
// ties asc idx) and perm_com (unselected, ascending idx).
// One CTA of 1024 threads per graph.
__global__ __launch_bounds__(1024) void sort_kernel(float* __restrict__ out_perm,
                                                    float* __restrict__ out_perm_com) {
    __shared__ unsigned long long keys[N_];
    __shared__ int flags[N_];
    __shared__ int scan[N_];

    const int g   = blockIdx.x;
    const int tid = threadIdx.x;
    const int base = g * N_;

    #pragma unroll
    for (int r = 0; r < 2; r++) {
        int i = tid + r * 1024;
        float sc = g_score[base + i];
        unsigned int k32 = ~ford(sc);              // ascending k32 == descending score
        keys[i] = ((unsigned long long)k32 << 32) | (unsigned int)i;
    }
    __syncthreads();

    // bitonic sort ascending (=> descending score, ties ascending local idx)
    for (int k = 2; k <= N_; k <<= 1) {
        for (int j = k >> 1; j > 0; j >>= 1) {
            #pragma unroll
            for (int r = 0; r < 2; r++) {
                int i = tid + r * 1024;
                int ixj = i ^ j;
                if (ixj > i) {
                    unsigned long long a = keys[i], bb = keys[ixj];
                    bool up = ((i & k) == 0);
                    if ((a > bb) == up) { keys[i] = bb; keys[ixj] = a; }
                }
            }
            __syncthreads();
        }
    }

    // flags: 1 = unselected
    flags[tid] = 1;
    flags[tid + 1024] = 1;
    __syncthreads();

    // top K_ = first 1024 sorted entries
    {
        int local = (int)(unsigned int)(keys[tid] & 0xFFFFFFFFull);
        flags[local] = 0;
        int gid = base + local;
        g_perm[g * K_ + tid]    = gid;
        out_perm[g * K_ + tid]  = (float)gid;
    }
    __syncthreads();

    // inclusive scan of flags
    scan[tid] = flags[tid];
    scan[tid + 1024] = flags[tid + 1024];
    __syncthreads();
    for (int off = 1; off < N_; off <<= 1) {
        int i0 = tid, i1 = tid + 1024;
        int v0 = scan[i0] + ((i0 >= off) ? scan[i0 - off] : 0);
        int v1 = scan[i1] + ((i1 >= off) ? scan[i1 - off] : 0);
        __syncthreads();
        scan[i0] = v0; scan[i1] = v1;
        __syncthreads();
    }

    #pragma unroll
    for (int r = 0; r < 2; r++) {
        int i = tid + r * 1024;
        if (flags[i]) {
            int pos = scan[i] - 1;                 // 0 .. N_-K_-1
            int gid = base + i;
            g_perm_com[g * (N_ - K_) + pos]   = gid;
            out_perm_com[g * (N_ - K_) + pos] = (float)gid;
        }
    }
}

// Emit feature_full (+score_sm), feature_dist, feature_com. One warp per row.
__global__ void emit_kernel(const float* __restrict__ feat,
                            float* __restrict__ out_dist,
                            float* __restrict__ out_com,
                            float* __restrict__ out_full,
                            float* __restrict__ out_sm) {
    int gtid = blockIdx.x * blockDim.x + threadIdx.x;
    int w    = gtid >> 5;
    int lane = gtid & 31;
    const int TW = BN_ + BK_ + BK_;
    if (w >= TW) return;

    int p;           // source node
    float* outp;     // destination row
    if (w < BN_) {
        p = w;
        outp = out_full + (size_t)w * D_;
        if (lane == 0) {
            float smax = fdeord(g_smax_ord);
            out_sm[w] = __expf(g_score[w] - smax) / g_sumexp;
        }
    } else if (w < BN_ + BK_) {
        int r = w - BN_;
        p = g_perm[r];
        outp = out_dist + (size_t)r * D_;
    } else {
        int r = w - BN_ - BK_;
        p = g_perm_com[r];
        outp = out_com + (size_t)r * D_;
    }

    float t = g_t[p];
    const float4* fr = reinterpret_cast<const float4*>(feat + (size_t)p * D_);
    float4 f = __ldg(fr + lane);
    f.x *= t; f.y *= t; f.z *= t; f.w *= t;
    reinterpret_cast<float4*>(outp)[lane] = f;
}

// ---------------- launch ----------------------------------------------------

extern "C" void kernel_launch(void* const* d_in, const int* in_sizes, int n_in,
                              void* d_out, int out_size) {
    const float* feature = (const float*)d_in[0];
    const float* W       = (const float*)d_in[1];
    const float* b       = (const float*)d_in[2];
    const int*   src     = (const int*)d_in[3];
    const int*   dst     = (const int*)d_in[4];

    float* out = (float*)d_out;
    float* out_dist     = out;                                  // BK_*D_
    float* out_com      = out + (size_t)BK_ * D_;               // BK_*D_
    float* out_full     = out + (size_t)2 * BK_ * D_;           // BN_*D_
    float* out_perm     = out + (size_t)2 * BK_ * D_ + (size_t)BN_ * D_;
    float* out_perm_com = out_perm + BK_;
    float* out_sm       = out_perm_com + BK_;

    init_kernel<<<(BN_ + 255) / 256, 256>>>();
    deg_kernel<<<(E_ + 255) / 256, 256>>>(src, dst);
    proj_kernel<<<(BN_ * 32 + 255) / 256, 256>>>(feature, W);
    scatter_kernel<<<(E_ + 255) / 256, 256>>>(src, dst);
    finalize_kernel<<<(BN_ + 255) / 256, 256>>>(b);
    sumexp_kernel<<<(BN_ + 255) / 256, 256>>>();
    sort_kernel<<<B_, 1024>>>(out_perm, out_perm_com);
    {
        const int TW = BN_ + BK_ + BK_;
        emit_kernel<<<((size_t)TW * 32 + 255) / 256, 256>>>(
            feature, out_dist, out_com, out_full, out_sm);
    }
}

// round 4
// speedup vs baseline: 1.6048x; 1.6048x over previous
#include <cuda_runtime.h>
#include <cuda_bf16.h>
#include <cstdint>

// Problem constants (fixed shapes)
static constexpr int B_   = 64;
static constexpr int N_   = 2048;
static constexpr int D_   = 128;
static constexpr int K_   = 1024;          // ceil(0.5 * N)
static constexpr int BN_  = B_ * N_;       // 131072 nodes
static constexpr int BK_  = B_ * K_;       // 65536 kept nodes
static constexpr int DEG_ = 32;
static constexpr int EPG_ = N_ * DEG_;     // 65536 edges per graph
static constexpr int NPC_ = 8;             // CTAs per graph (deg & scatter)
static constexpr int EPC_ = EPG_ / NPC_;   // 8192 edges per CTA
static constexpr int NCTA_ = B_ * NPC_;    // 512

// ---------------- scratch (device globals; no allocation allowed) ----------
__device__ int    g_odp[NCTA_ * N_];       // outdeg partials (4MB)
__device__ int    g_idp[NCTA_ * N_];       // indeg  partials (4MB)
__device__ double g_sp [NCTA_ * N_];       // score-sum partials (8MB)
__device__ int    g_outdeg[BN_];
__device__ double g_m[BN_];                // s / sqrt(outdeg)
__device__ float  g_score[BN_];
__device__ float  g_t[BN_];
__device__ int    g_perm[BK_];
__device__ int    g_perm_com[BK_];
__device__ float  g_sumexp;

// monotonic float->uint mapping (for sort keys)
__device__ __forceinline__ unsigned int ford(float f) {
    unsigned int u = __float_as_uint(f);
    return (u & 0x80000000u) ? ~u : (u | 0x80000000u);
}

// error-free addition: s + e == a + b exactly. s assigned last (alias-safe).
__device__ __forceinline__ void two_sum(float a, float b, float& s, float& e) {
    float s_ = a + b;
    float bb = s_ - a;
    e = (a - (s_ - bb)) + (b - bb);
    s = s_;
}

// ---------------- kernels ---------------------------------------------------

// Per-CTA SMEM histogram of src -> outdeg partials. Also zero g_sumexp.
__global__ __launch_bounds__(256) void deg_kernel(const int* __restrict__ src) {
    __shared__ int h[N_];
    const int c = blockIdx.x;            // 0..511
    const int g = c >> 3, sub = c & 7;
    const int tid = threadIdx.x;
    for (int i = tid; i < N_; i += 256) h[i] = 0;
    if (c == 0 && tid == 0) g_sumexp = 0.0f;
    __syncthreads();

    const int4* p = reinterpret_cast<const int4*>(src + g * EPG_ + sub * EPC_);
    #pragma unroll
    for (int it = 0; it < EPC_ / (256 * 4); ++it) {
        int4 v = p[tid + it * 256];
        atomicAdd(&h[v.x & (N_ - 1)], 1);
        atomicAdd(&h[v.y & (N_ - 1)], 1);
        atomicAdd(&h[v.z & (N_ - 1)], 1);
        atomicAdd(&h[v.w & (N_ - 1)], 1);
    }
    __syncthreads();
    for (int i = tid; i < N_; i += 256) g_odp[c * N_ + i] = h[i];
}

// Merge 8 outdeg partials per node (fixed order).
__global__ void odmerge_kernel() {
    int v = blockIdx.x * blockDim.x + threadIdx.x;
    if (v >= BN_) return;
    int g = v >> 11, l = v & (N_ - 1);
    int s = 0;
    #pragma unroll
    for (int p = 0; p < NPC_; ++p) s += g_odp[(g * NPC_ + p) * N_ + l];
    g_outdeg[v] = s;
}

// s = feature @ W via FP32 error-free (compensated) dot; m = s / sqrt(outdeg).
// One warp per node row.
__global__ void proj_kernel(const float* __restrict__ feat, const float* __restrict__ W) {
    int gtid = blockIdx.x * blockDim.x + threadIdx.x;
    int w    = gtid >> 5;
    int lane = gtid & 31;
    if (w >= BN_) return;
    float4 f  = __ldg(reinterpret_cast<const float4*>(feat) + (size_t)w * 32 + lane);
    float4 wv = __ldg(reinterpret_cast<const float4*>(W) + lane);

    float p0 = f.x * wv.x, e0 = fmaf(f.x, wv.x, -p0);
    float p1 = f.y * wv.y, e1 = fmaf(f.y, wv.y, -p1);
    float p2 = f.z * wv.z, e2 = fmaf(f.z, wv.z, -p2);
    float p3 = f.w * wv.w, e3 = fmaf(f.w, wv.w, -p3);

    float hi, lo, err;
    two_sum(p0, p1, hi, lo);
    two_sum(hi, p2, hi, err); lo += err;
    two_sum(hi, p3, hi, err); lo += err;
    lo += (e0 + e1) + (e2 + e3);

    #pragma unroll
    for (int o = 16; o > 0; o >>= 1) {
        float h2 = __shfl_xor_sync(0xFFFFFFFFu, hi, o);
        float l2 = __shfl_xor_sync(0xFFFFFFFFu, lo, o);
        two_sum(hi, h2, hi, err);
        lo += l2 + err;
    }
    if (lane == 0) {
        double s = (double)hi + (double)lo;
        int od = max(g_outdeg[w], 1);
        g_m[w] = s / sqrt((double)od);
    }
}

// Fused: indeg histogram (dst) + double score-sum in SMEM -> partials.
__global__ __launch_bounds__(256) void scatter_kernel(const int* __restrict__ src,
                                                      const int* __restrict__ dst) {
    __shared__ double acc[N_];   // 16KB
    __shared__ int    ih[N_];    // 8KB
    const int c = blockIdx.x;
    const int g = c >> 3, sub = c & 7;
    const int tid = threadIdx.x;
    for (int i = tid; i < N_; i += 256) { acc[i] = 0.0; ih[i] = 0; }
    __syncthreads();

    const int4* ps = reinterpret_cast<const int4*>(src + g * EPG_ + sub * EPC_);
    const int4* pd = reinterpret_cast<const int4*>(dst + g * EPG_ + sub * EPC_);
    const double* m = g_m + (size_t)g * N_;   // 16KB slice: L1-resident
    #pragma unroll
    for (int it = 0; it < EPC_ / (256 * 4); ++it) {
        int4 s4 = ps[tid + it * 256];
        int4 d4 = pd[tid + it * 256];
        int dx = d4.x & (N_ - 1), dy = d4.y & (N_ - 1);
        int dz = d4.z & (N_ - 1), dw = d4.w & (N_ - 1);
        atomicAdd(&acc[dx], m[s4.x & (N_ - 1)]); atomicAdd(&ih[dx], 1);
        atomicAdd(&acc[dy], m[s4.y & (N_ - 1)]); atomicAdd(&ih[dy], 1);
        atomicAdd(&acc[dz], m[s4.z & (N_ - 1)]); atomicAdd(&ih[dz], 1);
        atomicAdd(&acc[dw], m[s4.w & (N_ - 1)]); atomicAdd(&ih[dw], 1);
    }
    __syncthreads();
    for (int i = tid; i < N_; i += 256) {
        g_sp [c * N_ + i] = acc[i];
        g_idp[c * N_ + i] = ih[i];
    }
}

// score = sum(partials)/sqrt(indeg) + b (double, fixed order -> deterministic);
// t = tanh(score); accumulate sum of exp(score) (no max shift needed: |score| small).
__global__ void finalize_kernel(const float* __restrict__ b) {
    int v = blockIdx.x * blockDim.x + threadIdx.x;
    float sc = 0.0f, e = 0.0f;
    if (v < BN_) {
        int g = v >> 11, l = v & (N_ - 1);
        double S = 0.0;
        int id = 0;
        #pragma unroll
        for (int p = 0; p < NPC_; ++p) {
            S  += g_sp [(g * NPC_ + p) * N_ + l];
            id += g_idp[(g * NPC_ + p) * N_ + l];
        }
        double sd = S / sqrt((double)max(id, 1)) + (double)__ldg(b);
        sc = (float)sd;
        g_score[v] = sc;
        g_t[v] = tanhf(sc);
        e = __expf(sc);
    }
    __shared__ float sm[32];
    #pragma unroll
    for (int o = 16; o > 0; o >>= 1) e += __shfl_xor_sync(0xFFFFFFFFu, e, o);
    int lane = threadIdx.x & 31, wid = threadIdx.x >> 5;
    if (lane == 0) sm[wid] = e;
    __syncthreads();
    if (wid == 0) {
        e = (lane < (blockDim.x >> 5)) ? sm[lane] : 0.0f;
        #pragma unroll
        for (int o = 16; o > 0; o >>= 1) e += __shfl_xor_sync(0xFFFFFFFFu, e, o);
        if (lane == 0) atomicAdd(&g_sumexp, e);
    }
}

// register-phase bitonic compare-exchange (j <= 16, within warp)
__device__ __forceinline__ void reg_ex(unsigned long long& key, int i, int j, int k) {
    unsigned long long p = __shfl_xor_sync(0xFFFFFFFFu, key, j);
    bool up  = ((i & k) == 0);
    bool low = ((i & j) == 0);
    unsigned long long mn = key < p ? key : p;
    unsigned long long mx = key < p ? p : key;
    key = (low == up) ? mn : mx;
}

// Per-graph hybrid bitonic sort (SMEM for j>=32, registers for j<=16),
// then perm (top-K desc score, ties asc idx) and perm_com (unselected asc idx).
__global__ __launch_bounds__(1024) void sort_kernel(float* __restrict__ out_perm,
                                                    float* __restrict__ out_perm_com) {
    __shared__ unsigned long long keys[N_];
    __shared__ int flags[N_];
    __shared__ int scan[N_];

    const int g    = blockIdx.x;
    const int tid  = threadIdx.x;
    const int base = g * N_;
    const int i0 = tid, i1 = tid + 1024;

    unsigned long long k0, k1;
    {
        unsigned int a = ~ford(g_score[base + i0]);
        unsigned int b = ~ford(g_score[base + i1]);
        k0 = ((unsigned long long)a << 32) | (unsigned int)i0;
        k1 = ((unsigned long long)b << 32) | (unsigned int)i1;
    }

    // k = 2..32 entirely in registers
    #pragma unroll
    for (int k = 2; k <= 32; k <<= 1)
        for (int j = k >> 1; j >= 1; j >>= 1) { reg_ex(k0, i0, j, k); reg_ex(k1, i1, j, k); }

    // k = 64..2048: SMEM passes for j>=32, register passes for j<=16
    for (int k = 64; k <= N_; k <<= 1) {
        keys[i0] = k0; keys[i1] = k1;
        __syncthreads();
        for (int j = k >> 1; j >= 32; j >>= 1) {
            #pragma unroll
            for (int r = 0; r < 2; r++) {
                int i = tid + r * 1024;
                int ixj = i ^ j;
                if (ixj > i) {
                    unsigned long long a = keys[i], bb = keys[ixj];
                    bool up = ((i & k) == 0);
                    if ((a > bb) == up) { keys[i] = bb; keys[ixj] = a; }
                }
            }
            __syncthreads();
        }
        k0 = keys[i0]; k1 = keys[i1];
        #pragma unroll
        for (int j = 16; j >= 1; j >>= 1) { reg_ex(k0, i0, j, k); reg_ex(k1, i1, j, k); }
    }
    keys[i0] = k0; keys[i1] = k1;
    __syncthreads();

    // flags: 1 = unselected
    flags[i0] = 1; flags[i1] = 1;
    __syncthreads();

    // top K_ = first 1024 sorted entries
    {
        int local = (int)(unsigned int)(keys[tid] & 0xFFFFFFFFull);
        flags[local] = 0;
        int gid = base + local;
        g_perm[g * K_ + tid]   = gid;
        out_perm[g * K_ + tid] = (float)gid;
    }
    __syncthreads();

    // inclusive scan of flags
    scan[i0] = flags[i0];
    scan[i1] = flags[i1];
    __syncthreads();
    for (int off = 1; off < N_; off <<= 1) {
        int v0 = scan[i0] + ((i0 >= off) ? scan[i0 - off] : 0);
        int v1 = scan[i1] + ((i1 >= off) ? scan[i1 - off] : 0);
        __syncthreads();
        scan[i0] = v0; scan[i1] = v1;
        __syncthreads();
    }

    #pragma unroll
    for (int r = 0; r < 2; r++) {
        int i = tid + r * 1024;
        if (flags[i]) {
            int pos = scan[i] - 1;                 // 0 .. N_-K_-1
            int gid = base + i;
            g_perm_com[g * (N_ - K_) + pos]   = gid;
            out_perm_com[g * (N_ - K_) + pos] = (float)gid;
        }
    }
}

// Emit feature_full (+score_sm), feature_dist, feature_com. One warp per row.
__global__ void emit_kernel(const float* __restrict__ feat,
                            float* __restrict__ out_dist,
                            float* __restrict__ out_com,
                            float* __restrict__ out_full,
                            float* __restrict__ out_sm) {
    int gtid = blockIdx.x * blockDim.x + threadIdx.x;
    int w    = gtid >> 5;
    int lane = gtid & 31;
    const int TW = BN_ + BK_ + BK_;
    if (w >= TW) return;

    int p;           // source node
    float* outp;     // destination row
    if (w < BN_) {
        p = w;
        outp = out_full + (size_t)w * D_;
        if (lane == 0) {
            out_sm[w] = __expf(g_score[w]) / g_sumexp;
        }
    } else if (w < BN_ + BK_) {
        int r = w - BN_;
        p = g_perm[r];
        outp = out_dist + (size_t)r * D_;
    } else {
        int r = w - BN_ - BK_;
        p = g_perm_com[r];
        outp = out_com + (size_t)r * D_;
    }

    float t = g_t[p];
    float4 f = __ldg(reinterpret_cast<const float4*>(feat) + (size_t)p * 32 + lane);
    f.x *= t; f.y *= t; f.z *= t; f.w *= t;
    reinterpret_cast<float4*>(outp)[lane] = f;
}

// ---------------- launch ----------------------------------------------------

extern "C" void kernel_launch(void* const* d_in, const int* in_sizes, int n_in,
                              void* d_out, int out_size) {
    const float* feature = (const float*)d_in[0];
    const float* W       = (const float*)d_in[1];
    const float* b       = (const float*)d_in[2];
    const int*   src     = (const int*)d_in[3];
    const int*   dst     = (const int*)d_in[4];

    float* out = (float*)d_out;
    float* out_dist     = out;                                  // BK_*D_
    float* out_com      = out + (size_t)BK_ * D_;               // BK_*D_
    float* out_full     = out + (size_t)2 * BK_ * D_;           // BN_*D_
    float* out_perm     = out + (size_t)2 * BK_ * D_ + (size_t)BN_ * D_;
    float* out_perm_com = out_perm + BK_;
    float* out_sm       = out_perm_com + BK_;

    deg_kernel<<<NCTA_, 256>>>(src);
    odmerge_kernel<<<(BN_ + 255) / 256, 256>>>();
    proj_kernel<<<(BN_ * 32 + 255) / 256, 256>>>(feature, W);
    scatter_kernel<<<NCTA_, 256>>>(src, dst);
    finalize_kernel<<<(BN_ + 255) / 256, 256>>>(b);
    sort_kernel<<<B_, 1024>>>(out_perm, out_perm_com);
    {
        const int TW = BN_ + BK_ + BK_;
        emit_kernel<<<((size_t)TW * 32 + 255) / 256, 256>>>(
            feature, out_dist, out_com, out_full, out_sm);
    }
}